// round 14
// baseline (speedup 1.0000x reference)
#include <cuda_runtime.h>
#include <math.h>

#define Nn 50000
#define En 800000
#define Cc 16
#define Mm 32
#define Gg 8
#define CG (Cc*Gg)          // 128
#define NODES_PB 128        // nodes per layer1 block
#define HP 36               // hist smem row pitch (floats): 16B-aligned, 4-bank skew

// ---- scratch (module-static, allowed) ----
__device__ float g_smB1[Cc*Mm*Gg];   // softmax(B1, axis=M)   [c][m][g]
__device__ float g_R[Gg*Mm*Cc];      // R[g][m][i] = sum_l Q[i,l,g]*post0_tab[m][l,g]/norm0
__device__ float g_ll0[Mm*Gg];       // ll0_tab[m][g] = log(norm0(m,g))
__device__ int   g_hist[(size_t)Nn*Mm];  // per-node neighbor symbol histogram

// packed fp32x2 helpers (sm_100+ PTX; ptxas never emits these from C++)
#define FFMA2(d,a,b,c) asm("fma.rn.f32x2 %0, %1, %2, %3;" : "=l"(d) : "l"(a), "l"(b), "l"(c))
#define PACK2(d,x)     asm("mov.b64 %0, {%1, %1};" : "=l"(d) : "f"(x))
#define UNPK2(lo,hi,v) asm("mov.b64 {%0, %1}, %2;" : "=f"(lo), "=f"(hi) : "l"(v))

__device__ __forceinline__ float wmax32(float v){
    #pragma unroll
    for (int o=16;o;o>>=1) v = fmaxf(v, __shfl_xor_sync(0xffffffffu, v, o));
    return v;
}
__device__ __forceinline__ float wsum32(float v){
    #pragma unroll
    for (int o=16;o;o>>=1) v += __shfl_xor_sync(0xffffffffu, v, o);
    return v;
}
__device__ __forceinline__ float gmax16(float v){
    #pragma unroll
    for (int o=8;o;o>>=1) v = fmaxf(v, __shfl_xor_sync(0xffffffffu, v, o));
    return v;
}
__device__ __forceinline__ float gsum16(float v){
    #pragma unroll
    for (int o=8;o;o>>=1) v += __shfl_xor_sync(0xffffffffu, v, o);
    return v;
}

// ---------------------------------------------------------------------------
// 1) Fused init, 1024-thread blocks.
//    Block 0: lane-parallel softmaxes (shfl reductions, ~11 expf/thread)
//             into smem, then R / ll0 / smB1 tables.
//    Blocks >= 1: zero the histogram.
// ---------------------------------------------------------------------------
__global__ void __launch_bounds__(1024)
k_init(const float* __restrict__ B0, const float* __restrict__ Pi,
       const float* __restrict__ B1, const float* __restrict__ Q)
{
    if (blockIdx.x > 0) {
        int i = (blockIdx.x - 1) * 1024 + threadIdx.x;
        if (i < Nn * Mm / 4)
            reinterpret_cast<int4*>(g_hist)[i] = make_int4(0, 0, 0, 0);
        return;
    }

    __shared__ float s_B0[Cc*Mm*Gg];   // 16 KB  [c][m][g]
    __shared__ float s_Q [Cc*Cc*Gg];   //  8 KB  [i][l][g]
    __shared__ float s_Pi[Cc*Gg];      // 512 B  [c][g]

    int t = threadIdx.x, w = t >> 5, lane = t & 31;

    // B0 & B1: 128 (c,g)-rows each; warp w handles rows 4w..4w+3, lane = m.
    #pragma unroll
    for (int rr = 0; rr < 4; rr++) {
        int row = w*4 + rr; int c = row >> 3, g = row & 7;
        {
            float v = B0[c*Mm*Gg + lane*Gg + g];
            float e = expf(v - wmax32(v));
            s_B0[c*Mm*Gg + lane*Gg + g] = e / wsum32(e);
        }
        {
            float v = B1[c*Mm*Gg + lane*Gg + g];
            float e = expf(v - wmax32(v));
            g_smB1[c*Mm*Gg + lane*Gg + g] = e / wsum32(e);
        }
    }
    // Q: 128 (l,g)-columns, 16 i-values each; two columns per warp-pass
    // (lanes 0-15 one column, 16-31 the other), 16-lane-group reductions.
    #pragma unroll
    for (int p = 0; p < 2; p++) {
        int cidx = w*4 + p*2 + (lane >> 4);   // 0..127
        int l = cidx >> 3, g = cidx & 7, i = lane & 15;
        float v = Q[i*Cc*Gg + l*Gg + g];
        float e = expf(v - gmax16(v));
        s_Q[i*Cc*Gg + l*Gg + g] = e / gsum16(e);
    }
    // Pi: 8 g-columns of 16 c-values; warps 0..3, two columns each.
    if (w < 4) {
        int g = w*2 + (lane >> 4); int c = lane & 15;
        float v = Pi[c*Gg + g];
        float e = expf(v - gmax16(v));
        s_Pi[c*Gg + g] = e / gsum16(e);
    }
    __syncthreads();

    // R + ll0: thread t -> (m,g) = t>>2 decoded, i-quad (t&3)*4.
    {
        int mg = t >> 2; int m = mg >> 3, g = mg & 7; int i0 = (t & 3) * 4;
        float u[Cc]; float s = 0.f;
        #pragma unroll
        for (int l = 0; l < Cc; l++) {
            u[l] = s_Pi[l*Gg + g] * s_B0[l*Mm*Gg + m*Gg + g];
            s += u[l];
        }
        if ((t & 3) == 0) g_ll0[m*Gg + g] = logf(s);
        float inv = 1.f / s;
        #pragma unroll
        for (int i = i0; i < i0 + 4; i++) {
            float acc = 0.f;
            #pragma unroll
            for (int l = 0; l < Cc; l++)
                acc += s_Q[i*Cc*Gg + l*Gg + g] * u[l];
            g_R[g*Mm*Cc + m*Cc + i] = acc * inv;
        }
    }
}

// ---------------------------------------------------------------------------
// 2) Histogram scatter: 4 edges per thread.  hist[src][x[dst]] += 1
// ---------------------------------------------------------------------------
__global__ void k_scatter(const int* __restrict__ ei, const int* __restrict__ x)
{
    int tid = blockIdx.x * blockDim.x + threadIdx.x;
    if (tid >= En / 4) return;
    int e0 = tid * 4;

    const int4 S = *reinterpret_cast<const int4*>(ei + e0);        // 4 src
    const int4 D = *reinterpret_cast<const int4*>(ei + En + e0);   // 4 dst

    int x0 = __ldg(x + D.x);
    int x1 = __ldg(x + D.y);
    int x2 = __ldg(x + D.z);
    int x3 = __ldg(x + D.w);

    atomicAdd(&g_hist[(size_t)S.x * Mm + x0], 1);
    atomicAdd(&g_hist[(size_t)S.y * Mm + x1], 1);
    atomicAdd(&g_hist[(size_t)S.z * Mm + x2], 1);
    atomicAdd(&g_hist[(size_t)S.w * Mm + x3], 1);
}

// ---------------------------------------------------------------------------
// 3) Layer 1 (+ ll0 lookup). Block = 256 threads / 128 nodes; thread (q,g)
//    processes 4 nodes. Inner product in packed fp32x2: per m, 4 LDS.128 of
//    R[g][m][:] feed 32 FFMA2 (4 nodes x 8 pairs); hist read as one LDS.128
//    per node per 4 m's. s_R rows padded 516 (8 g-rows on disjoint banks),
//    s_h rows padded HP=36 (16B-aligned, 4-bank row skew).
// ---------------------------------------------------------------------------
__global__ void k_layer1(const int* __restrict__ x, float* __restrict__ out)
{
    __shared__ float s_R[Gg * 516];          // 16.5 KB
    __shared__ float s_h[NODES_PB * HP];     // 18.4 KB
    __shared__ int   s_x[NODES_PB];

    int t   = threadIdx.x;
    int bn0 = blockIdx.x * NODES_PB;

    // cooperative load of R: thread t -> 16 consecutive floats of g-row (t>>5)
    {
        int g   = t >> 5;
        int rem = (t & 31) * 16;
        const float4* src = reinterpret_cast<const float4*>(g_R + g * (Mm*Cc) + rem);
        float4*       dst = reinterpret_cast<float4*>(s_R + g * 516 + rem);
        dst[0] = src[0]; dst[1] = src[1]; dst[2] = src[2]; dst[3] = src[3];
    }
    // cooperative load of hist (int -> float): thread t -> half a row (16 vals)
    {
        int row = t >> 1;
        int cb  = (t & 1) * 16;
        if (bn0 + row < Nn) {
            const int4* src = reinterpret_cast<const int4*>(
                g_hist + (size_t)(bn0 + row) * Mm + cb);
            float* dp = s_h + row * HP + cb;
            #pragma unroll
            for (int q = 0; q < 4; q++) {
                int4 v = src[q];
                dp[q*4+0] = (float)v.x; dp[q*4+1] = (float)v.y;
                dp[q*4+2] = (float)v.z; dp[q*4+3] = (float)v.w;
            }
        }
    }
    if (t < NODES_PB && bn0 + t < Nn) s_x[t] = x[bn0 + t];
    __syncthreads();

    int q = t >> 3, g = t & 7;          // q: 0..31 -> nodes q*4 .. q*4+3
    int nb = q * 4;

    unsigned long long tv2[4][8];
    #pragma unroll
    for (int j = 0; j < 4; j++)
        #pragma unroll
        for (int k = 0; k < 8; k++) tv2[j][k] = 0ULL;
    float cnt[4] = {0.f, 0.f, 0.f, 0.f};

    const float* Rg = s_R + g * 516;
    const float* h0 = s_h + (nb + 0) * HP;
    const float* h1 = s_h + (nb + 1) * HP;
    const float* h2 = s_h + (nb + 2) * HP;
    const float* h3 = s_h + (nb + 3) * HP;

    #pragma unroll
    for (int mo = 0; mo < 8; mo++) {
        float4 hA = *reinterpret_cast<const float4*>(h0 + mo*4);
        float4 hB = *reinterpret_cast<const float4*>(h1 + mo*4);
        float4 hC = *reinterpret_cast<const float4*>(h2 + mo*4);
        float4 hD = *reinterpret_cast<const float4*>(h3 + mo*4);
        float fa[4] = {hA.x, hA.y, hA.z, hA.w};
        float fb[4] = {hB.x, hB.y, hB.z, hB.w};
        float fc[4] = {hC.x, hC.y, hC.z, hC.w};
        float fd[4] = {hD.x, hD.y, hD.z, hD.w};

        #pragma unroll
        for (int mm = 0; mm < 4; mm++) {
            const ulonglong2* r2 = reinterpret_cast<const ulonglong2*>(
                Rg + (mo*4 + mm) * Cc);
            ulonglong2 Ra = r2[0], Rb = r2[1], Rc = r2[2], Rd = r2[3];
            unsigned long long rp[8] = {Ra.x, Ra.y, Rb.x, Rb.y,
                                        Rc.x, Rc.y, Rd.x, Rd.y};
            float a0 = fa[mm], a1 = fb[mm], a2 = fc[mm], a3 = fd[mm];
            cnt[0] += a0; cnt[1] += a1; cnt[2] += a2; cnt[3] += a3;
            unsigned long long p0, p1, p2, p3;
            PACK2(p0, a0); PACK2(p1, a1); PACK2(p2, a2); PACK2(p3, a3);
            #pragma unroll
            for (int k = 0; k < 8; k++) {
                FFMA2(tv2[0][k], p0, rp[k], tv2[0][k]);
                FFMA2(tv2[1][k], p1, rp[k], tv2[1][k]);
                FFMA2(tv2[2][k], p2, rp[k], tv2[2][k]);
                FFMA2(tv2[3][k], p3, rp[k], tv2[3][k]);
            }
        }
    }

    float* p1out = out + (size_t)Nn * 2 * Gg;

    #pragma unroll
    for (int j = 0; j < 4; j++) {
        int n = bn0 + nb + j;
        if (n >= Nn) break;
        int xm = s_x[nb + j];

        float tv[Cc];
        #pragma unroll
        for (int k = 0; k < 8; k++) UNPK2(tv[2*k], tv[2*k+1], tv2[j][k]);

        float inv_cnt = 1.f / fmaxf(cnt[j], 1.f);
        float v[Cc]; float norm = 0.f;
        #pragma unroll
        for (int i = 0; i < Cc; i++) {
            float wv = g_smB1[i*Mm*Gg + xm*Gg + g] * tv[i] * inv_cnt;
            v[i] = wv;
            norm += wv;
        }
        out[(size_t)n * (2*Gg) + g]      = g_ll0[xm*Gg + g];
        out[(size_t)n * (2*Gg) + Gg + g] = logf(norm);
        float invn = 1.f / norm;
        size_t pbase = (size_t)n * CG + g;
        #pragma unroll
        for (int i = 0; i < Cc; i++) p1out[pbase + i*Gg] = v[i] * invn;
    }
}

// ---------------------------------------------------------------------------
extern "C" void kernel_launch(void* const* d_in, const int* in_sizes, int n_in,
                              void* d_out, int out_size)
{
    const int*   x  = (const int*)  d_in[0];
    const int*   ei = (const int*)  d_in[1];   // [2, E]
    const float* B0 = (const float*)d_in[2];
    const float* Pi = (const float*)d_in[3];
    const float* B1 = (const float*)d_in[4];
    const float* Q  = (const float*)d_in[5];
    float* out = (float*)d_out;

    // block 0: softmax+tables; blocks 1..391: zero hist (391*1024 >= 400000 int4)
    k_init<<<392, 1024>>>(B0, Pi, B1, Q);
    k_scatter<<<(En / 4 + 255) / 256, 256>>>(ei, x);
    k_layer1<<<(Nn + NODES_PB - 1) / NODES_PB, 256>>>(x, out);
}

// round 15
// speedup vs baseline: 1.8015x; 1.8015x over previous
#include <cuda_runtime.h>
#include <math.h>

#define Nn 50000
#define En 800000
#define Cc 16
#define Mm 32
#define Gg 8
#define CG (Cc*Gg)          // 128
#define NODES_PB 128        // nodes per layer1 block

// ---- scratch (module-static, allowed) ----
__device__ float g_smB1[Cc*Mm*Gg];   // softmax(B1, axis=M)   [c][m][g]
__device__ float g_R[Gg*Mm*Cc];      // R[g][m][i] = sum_l Q[i,l,g]*post0_tab[m][l,g]/norm0
__device__ float g_ll0[Mm*Gg];       // ll0_tab[m][g] = log(norm0(m,g))
__device__ int   g_hist[(size_t)Nn*Mm];  // per-node neighbor symbol histogram
// INVARIANT: g_hist is all-zero at kernel_launch entry (zero-init at load;
// k_layer1 re-zeroes the rows it consumed, so every execution restores it).

// ---------------------------------------------------------------------------
// 1) Fused scatter + table build.
//    Block 0   : softmaxes (no max-shift; inputs bounded +-5) + R/ll0/smB1.
//    Blocks >=1: histogram scatter, 4 edges/thread: hist[src][x[dst]] += 1.
//    The serial table build overlaps the edge blocks; both finish before
//    k_layer1 (kernel boundary).
// ---------------------------------------------------------------------------
__global__ void k_scatter(const int* __restrict__ ei, const int* __restrict__ x,
                          const float* __restrict__ B0, const float* __restrict__ Pi,
                          const float* __restrict__ B1, const float* __restrict__ Q)
{
    __shared__ float s_B0[Cc*Mm*Gg];   // 16 KB  [c][m][g]
    __shared__ float s_Q [Cc*Cc*Gg];   //  8 KB  [i][l][g]
    __shared__ float s_Pi[Cc*Gg];      // 512 B  [c][g]

    if (blockIdx.x > 0) {
        int tid = (blockIdx.x - 1) * blockDim.x + threadIdx.x;
        if (tid >= En / 4) return;
        int e0 = tid * 4;

        const int4 S = *reinterpret_cast<const int4*>(ei + e0);        // 4 src
        const int4 D = *reinterpret_cast<const int4*>(ei + En + e0);   // 4 dst

        int x0 = __ldg(x + D.x);
        int x1 = __ldg(x + D.y);
        int x2 = __ldg(x + D.z);
        int x3 = __ldg(x + D.w);

        atomicAdd(&g_hist[(size_t)S.x * Mm + x0], 1);
        atomicAdd(&g_hist[(size_t)S.y * Mm + x1], 1);
        atomicAdd(&g_hist[(size_t)S.z * Mm + x2], 1);
        atomicAdd(&g_hist[(size_t)S.w * Mm + x3], 1);
        return;
    }

    // ---- block 0: table build ----
    int t = threadIdx.x;

    if (t < 128) {
        int g = t & 7, r = t >> 3;
        // B0 row (c=r, g): softmax over m (no max-shift)
        float e[Mm]; float s = 0.f;
        #pragma unroll
        for (int m = 0; m < Mm; m++) { e[m] = expf(B0[r*Mm*Gg + m*Gg + g]); s += e[m]; }
        float inv = 1.f / s;
        #pragma unroll
        for (int m = 0; m < Mm; m++) s_B0[r*Mm*Gg + m*Gg + g] = e[m] * inv;

        // Q column (l=r, g): softmax over i
        float eq[Cc]; float sq = 0.f;
        #pragma unroll
        for (int i = 0; i < Cc; i++) { eq[i] = expf(Q[i*Cc*Gg + r*Gg + g]); sq += eq[i]; }
        float invq = 1.f / sq;
        #pragma unroll
        for (int i = 0; i < Cc; i++) s_Q[i*Cc*Gg + r*Gg + g] = eq[i] * invq;

        // Pi column g (threads 0..7): softmax over c
        if (t < Gg) {
            float ep[Cc]; float sp = 0.f;
            #pragma unroll
            for (int c = 0; c < Cc; c++) { ep[c] = expf(Pi[c*Gg + t]); sp += ep[c]; }
            float invp = 1.f / sp;
            #pragma unroll
            for (int c = 0; c < Cc; c++) s_Pi[c*Gg + t] = ep[c] * invp;
        }
    } else {
        // B1 row: threads 128..255 -> (c = (t-128)>>3, g = (t-128)&7),
        // written straight to global (consumed only by k_layer1).
        int t2 = t - 128;
        int g = t2 & 7, r = t2 >> 3;
        float e[Mm]; float s = 0.f;
        #pragma unroll
        for (int m = 0; m < Mm; m++) { e[m] = expf(B1[r*Mm*Gg + m*Gg + g]); s += e[m]; }
        float inv = 1.f / s;
        #pragma unroll
        for (int m = 0; m < Mm; m++) g_smB1[r*Mm*Gg + m*Gg + g] = e[m] * inv;
    }
    __syncthreads();

    // R + ll0 tables: thread t -> (m = t>>3, g = t&7). 256 threads = 32m x 8g.
    {
        int m = t >> 3, g = t & 7;
        float u[Cc]; float s = 0.f;
        #pragma unroll
        for (int l = 0; l < Cc; l++) {
            u[l] = s_Pi[l*Gg + g] * s_B0[l*Mm*Gg + m*Gg + g];
            s += u[l];
        }
        g_ll0[m*Gg + g] = logf(s);
        float inv = 1.f / s;
        #pragma unroll
        for (int i = 0; i < Cc; i++) {
            float acc = 0.f;
            #pragma unroll
            for (int l = 0; l < Cc; l++)
                acc += s_Q[i*Cc*Gg + l*Gg + g] * u[l];
            g_R[g*Mm*Cc + m*Cc + i] = acc * inv;
        }
    }
}

// ---------------------------------------------------------------------------
// 2) Layer 1 (+ ll0 lookup). Block = 256 threads covering 128 nodes.
//    Thread (q = t>>3, g = t&7) processes FOUR nodes so each R[g][m][:]
//    tile load (4x LDS.128) feeds 64 FMAs. hist staged in smem as floats;
//    each thread ZEROES the hist cells it just read (self-cleaning for the
//    next graph replay). s_R rows padded 516, s_h rows padded 33.
// ---------------------------------------------------------------------------
__global__ void k_layer1(const int* __restrict__ x, float* __restrict__ out)
{
    __shared__ float s_R[Gg * 516];          // 16.5 KB
    __shared__ float s_h[NODES_PB * 33];     // 16.9 KB
    __shared__ int   s_x[NODES_PB];

    int t   = threadIdx.x;
    int bn0 = blockIdx.x * NODES_PB;

    // cooperative load of R: thread t -> 16 consecutive floats of g-row (t>>5)
    {
        int g   = t >> 5;
        int rem = (t & 31) * 16;
        const float4* src = reinterpret_cast<const float4*>(g_R + g * (Mm*Cc) + rem);
        float4*       dst = reinterpret_cast<float4*>(s_R + g * 516 + rem);
        dst[0] = src[0]; dst[1] = src[1]; dst[2] = src[2]; dst[3] = src[3];
    }
    // cooperative load of hist (int -> float) + immediate re-zero of the
    // exact cells this thread read (block owns its rows; no cross-thread
    // hazard since reader == writer per cell).
    {
        int row = t >> 1;
        int cb  = (t & 1) * 16;
        if (bn0 + row < Nn) {
            int4* src = reinterpret_cast<int4*>(
                g_hist + (size_t)(bn0 + row) * Mm + cb);
            float* dp = s_h + row * 33 + cb;
            const int4 z4 = make_int4(0, 0, 0, 0);
            #pragma unroll
            for (int q = 0; q < 4; q++) {
                int4 v = src[q];
                dp[q*4+0] = (float)v.x; dp[q*4+1] = (float)v.y;
                dp[q*4+2] = (float)v.z; dp[q*4+3] = (float)v.w;
                src[q] = z4;
            }
        }
    }
    if (t < NODES_PB && bn0 + t < Nn) s_x[t] = x[bn0 + t];
    __syncthreads();

    int q = t >> 3, g = t & 7;          // q: 0..31 -> nodes q*4 .. q*4+3
    int nb = q * 4;

    float tv[4][Cc];
    #pragma unroll
    for (int j = 0; j < 4; j++)
        #pragma unroll
        for (int i = 0; i < Cc; i++) tv[j][i] = 0.f;
    float cnt[4] = {0.f, 0.f, 0.f, 0.f};

    const float* Rg = s_R + g * 516;
    const float* h0 = s_h + (nb + 0) * 33;
    const float* h1 = s_h + (nb + 1) * 33;
    const float* h2 = s_h + (nb + 2) * 33;
    const float* h3 = s_h + (nb + 3) * 33;

    #pragma unroll 4
    for (int m = 0; m < Mm; m++) {
        const float4* r4 = reinterpret_cast<const float4*>(Rg + m * Cc);
        float4 r0 = r4[0], r1 = r4[1], r2 = r4[2], r3 = r4[3];
        float a0 = h0[m], a1 = h1[m], a2 = h2[m], a3 = h3[m];
        cnt[0] += a0; cnt[1] += a1; cnt[2] += a2; cnt[3] += a3;

        tv[0][ 0] += a0*r0.x; tv[0][ 1] += a0*r0.y; tv[0][ 2] += a0*r0.z; tv[0][ 3] += a0*r0.w;
        tv[0][ 4] += a0*r1.x; tv[0][ 5] += a0*r1.y; tv[0][ 6] += a0*r1.z; tv[0][ 7] += a0*r1.w;
        tv[0][ 8] += a0*r2.x; tv[0][ 9] += a0*r2.y; tv[0][10] += a0*r2.z; tv[0][11] += a0*r2.w;
        tv[0][12] += a0*r3.x; tv[0][13] += a0*r3.y; tv[0][14] += a0*r3.z; tv[0][15] += a0*r3.w;

        tv[1][ 0] += a1*r0.x; tv[1][ 1] += a1*r0.y; tv[1][ 2] += a1*r0.z; tv[1][ 3] += a1*r0.w;
        tv[1][ 4] += a1*r1.x; tv[1][ 5] += a1*r1.y; tv[1][ 6] += a1*r1.z; tv[1][ 7] += a1*r1.w;
        tv[1][ 8] += a1*r2.x; tv[1][ 9] += a1*r2.y; tv[1][10] += a1*r2.z; tv[1][11] += a1*r2.w;
        tv[1][12] += a1*r3.x; tv[1][13] += a1*r3.y; tv[1][14] += a1*r3.z; tv[1][15] += a1*r3.w;

        tv[2][ 0] += a2*r0.x; tv[2][ 1] += a2*r0.y; tv[2][ 2] += a2*r0.z; tv[2][ 3] += a2*r0.w;
        tv[2][ 4] += a2*r1.x; tv[2][ 5] += a2*r1.y; tv[2][ 6] += a2*r1.z; tv[2][ 7] += a2*r1.w;
        tv[2][ 8] += a2*r2.x; tv[2][ 9] += a2*r2.y; tv[2][10] += a2*r2.z; tv[2][11] += a2*r2.w;
        tv[2][12] += a2*r3.x; tv[2][13] += a2*r3.y; tv[2][14] += a2*r3.z; tv[2][15] += a2*r3.w;

        tv[3][ 0] += a3*r0.x; tv[3][ 1] += a3*r0.y; tv[3][ 2] += a3*r0.z; tv[3][ 3] += a3*r0.w;
        tv[3][ 4] += a3*r1.x; tv[3][ 5] += a3*r1.y; tv[3][ 6] += a3*r1.z; tv[3][ 7] += a3*r1.w;
        tv[3][ 8] += a3*r2.x; tv[3][ 9] += a3*r2.y; tv[3][10] += a3*r2.z; tv[3][11] += a3*r2.w;
        tv[3][12] += a3*r3.x; tv[3][13] += a3*r3.y; tv[3][14] += a3*r3.z; tv[3][15] += a3*r3.w;
    }

    float* p1 = out + (size_t)Nn * 2 * Gg;

    #pragma unroll
    for (int j = 0; j < 4; j++) {
        int n = bn0 + nb + j;
        if (n >= Nn) break;
        int xm = s_x[nb + j];
        float inv_cnt = 1.f / fmaxf(cnt[j], 1.f);
        float v[Cc]; float norm = 0.f;
        #pragma unroll
        for (int i = 0; i < Cc; i++) {
            float w = g_smB1[i*Mm*Gg + xm*Gg + g] * tv[j][i] * inv_cnt;
            v[i] = w;
            norm += w;
        }
        out[(size_t)n * (2*Gg) + g]      = g_ll0[xm*Gg + g];
        out[(size_t)n * (2*Gg) + Gg + g] = logf(norm);
        float invn = 1.f / norm;
        size_t pbase = (size_t)n * CG + g;
        #pragma unroll
        for (int i = 0; i < Cc; i++) p1[pbase + i*Gg] = v[i] * invn;
    }
}

// ---------------------------------------------------------------------------
extern "C" void kernel_launch(void* const* d_in, const int* in_sizes, int n_in,
                              void* d_out, int out_size)
{
    const int*   x  = (const int*)  d_in[0];
    const int*   ei = (const int*)  d_in[1];   // [2, E]
    const float* B0 = (const float*)d_in[2];
    const float* Pi = (const float*)d_in[3];
    const float* B1 = (const float*)d_in[4];
    const float* Q  = (const float*)d_in[5];
    float* out = (float*)d_out;

    // block 0: table build; blocks 1..782: edge scatter (4 edges/thread)
    k_scatter<<<1 + (En / 4 + 255) / 256, 256>>>(ei, x, B0, Pi, B1, Q);
    k_layer1<<<(Nn + NODES_PB - 1) / NODES_PB, 256>>>(x, out);
}